// round 16
// baseline (speedup 1.0000x reference)
#include <cuda_runtime.h>
#include <cuda_fp16.h>
#include <cstdint>

#define HIDDEN 128
#define MAX_NODES 50000
#define MAX_EDGES 500000
#define SCAN_CHUNK 256
#define MAX_SBLOCKS ((MAX_NODES + SCAN_CHUNK - 1) / SCAN_CHUNK)   // 196

// Scratch (static __device__ arrays — zero-initialized at load; no allocation).
__device__ uint2 g_feah[MAX_NODES * 32];           // fea as fp16 (4 halfs / uint2)
__device__ uint2 g_learn1h[MAX_NODES * 32];        // learn1 as fp16
__device__ int   g_counts[MAX_NODES];              // INVARIANT: zero at call entry
__device__ int   g_offsets[MAX_NODES + 1];         // padded-CSR offsets (mult of 4)
__device__ int   g_rank[MAX_EDGES];
__device__ int   g_bsum[MAX_SBLOCKS];
// packed edges: low 16 bits = col (n_nodes < 65536), high 16 = fp16 val bits.
// pad word 0u = (col 0, val 0.0) -> contributes nothing.
__device__ __align__(16) unsigned int g_edges[MAX_EDGES + 3 * MAX_NODES];

// ---------------------------------------------------------------------------
// helpers
// ---------------------------------------------------------------------------
__device__ __forceinline__ uint2 pack4h(float4 a) {
    __half2 h01 = __floats2half2_rn(a.x, a.y);
    __half2 h23 = __floats2half2_rn(a.z, a.w);
    uint2 g;
    g.x = *reinterpret_cast<uint32_t*>(&h01);
    g.y = *reinterpret_cast<uint32_t*>(&h23);
    return g;
}

__device__ __forceinline__ float4 unpack4h(uint2 g) {
    __half2 h01 = *reinterpret_cast<__half2*>(&g.x);
    __half2 h23 = *reinterpret_cast<__half2*>(&g.y);
    float2 f01 = __half22float2(h01);
    float2 f23 = __half22float2(h23);
    return make_float4(f01.x, f01.y, f23.x, f23.y);
}

__device__ __forceinline__ void fma4h(float4& acc, float v, uint2 g) {
    float4 f = unpack4h(g);
    acc.x += v * f.x; acc.y += v * f.y; acc.z += v * f.z; acc.w += v * f.w;
}

__device__ __forceinline__ float edge_val(unsigned int e) {
    return __half2float(__ushort_as_half((unsigned short)(e >> 16)));
}
__device__ __forceinline__ unsigned int edge_col(unsigned int e) {
    return e & 0xFFFFu;
}

// ---------------------------------------------------------------------------
// 1) histogram + within-row rank (counts pre-zeroed invariant)
// ---------------------------------------------------------------------------
__global__ void hist_rank_kernel(const int* __restrict__ row,
                                 int* __restrict__ counts,
                                 int* __restrict__ rank, int n_edges) {
    int e = blockIdx.x * blockDim.x + threadIdx.x;
    if (e < n_edges) rank[e] = atomicAdd(&counts[__ldg(row + e)], 1);
}

// ---------------------------------------------------------------------------
// 2) per-256-chunk block SUMS of PADDED counts — shfl reduction
// ---------------------------------------------------------------------------
__global__ void __launch_bounds__(SCAN_CHUNK)
scan_bsum_kernel(const int* __restrict__ counts,
                 int* __restrict__ bsum, int n) {
    __shared__ int wsum[8];
    int t = threadIdx.x;
    int lane = t & 31, wid = t >> 5;
    int i = blockIdx.x * SCAN_CHUNK + t;
    int v = (i < n) ? ((__ldg(counts + i) + 3) & ~3) : 0;
    #pragma unroll
    for (int off = 16; off > 0; off >>= 1)
        v += __shfl_xor_sync(0xFFFFFFFFu, v, off);
    if (lane == 0) wsum[wid] = v;
    __syncthreads();
    if (t == 0) {
        int s = 0;
        #pragma unroll
        for (int k = 0; k < 8; k++) s += wsum[k];
        bsum[blockIdx.x] = s;
    }
}

// ---------------------------------------------------------------------------
// 3) final scan: shfl scans of bsums + block-local padded counts ->
//    exclusive offsets (multiple of 4); writes zero-pad edges.
// ---------------------------------------------------------------------------
__global__ void __launch_bounds__(SCAN_CHUNK)
scan_offsets_pad_kernel(const int* __restrict__ counts,
                        const int* __restrict__ bsum,
                        int* __restrict__ offsets,
                        unsigned int* __restrict__ edges,
                        int n, int nblocks) {
    __shared__ int sb[SCAN_CHUNK];
    __shared__ int wsum[8];
    __shared__ int wsum2[8];
    const int t = threadIdx.x;
    const int b = blockIdx.x;
    const int lane = t & 31, wid = t >> 5;

    int vb = (t < nblocks) ? __ldg(bsum + t) : 0;
    int sv = vb;
    #pragma unroll
    for (int off = 1; off < 32; off <<= 1) {
        int u = __shfl_up_sync(0xFFFFFFFFu, sv, off);
        if (lane >= off) sv += u;
    }
    if (lane == 31) wsum[wid] = sv;
    __syncthreads();
    if (t < 8) {
        int w = wsum[t];
        #pragma unroll
        for (int off = 1; off < 8; off <<= 1) {
            int u = __shfl_up_sync(0xFFu, w, off);
            if (t >= off) w += u;
        }
        wsum[t] = w;
    }
    __syncthreads();
    sb[t] = sv + ((wid > 0) ? wsum[wid - 1] : 0);
    __syncthreads();
    int bpref = (b > 0) ? sb[b - 1] : 0;

    int i = b * SCAN_CHUNK + t;
    int c  = (i < n) ? __ldg(counts + i) : 0;
    int cp = (c + 3) & ~3;
    int v = cp;
    #pragma unroll
    for (int off = 1; off < 32; off <<= 1) {
        int u = __shfl_up_sync(0xFFFFFFFFu, v, off);
        if (lane >= off) v += u;
    }
    if (lane == 31) wsum2[wid] = v;
    __syncthreads();
    if (t < 8) {
        int w = wsum2[t];
        #pragma unroll
        for (int off = 1; off < 8; off <<= 1) {
            int u = __shfl_up_sync(0xFFu, w, off);
            if (t >= off) w += u;
        }
        wsum2[t] = w;
    }
    __syncthreads();
    int excl = v - cp + ((wid > 0) ? wsum2[wid - 1] : 0);

    int run = bpref + excl;
    if (i < n) {
        offsets[i] = run;
        for (int j = c; j < cp; j++) edges[run + j] = 0u;   // pad edges
    }
    if (b == 0 && t == 0) offsets[n] = sb[nblocks - 1];
}

// ---------------------------------------------------------------------------
// 4) permute edges (2 edges/thread, no atomics)  +  fp16 convert of fea.
//    The convert loop is independent grid-stride work that fills the
//    scoreboard-stall shadows of the scattered permute gathers/stores.
// ---------------------------------------------------------------------------
__global__ void permute_convert_kernel(const int* __restrict__ row,
                                       const int* __restrict__ col,
                                       const float* __restrict__ val,
                                       const int* __restrict__ rank,
                                       const int* __restrict__ offsets,
                                       unsigned int* __restrict__ edges,
                                       const float4* __restrict__ fea,
                                       uint2* __restrict__ feah,
                                       int n_edges, int total4) {
    int tid = blockIdx.x * blockDim.x + threadIdx.x;
    int nth = gridDim.x * blockDim.x;

    // ---- permute: issue the long-latency scattered work first ----
    int base = tid * 2;
    if (base + 2 <= n_edges) {
        int2   r = __ldg((const int2*)  (row  + base));
        int2   c = __ldg((const int2*)  (col  + base));
        int2   k = __ldg((const int2*)  (rank + base));
        float2 v = __ldg((const float2*)(val  + base));
        int o0 = __ldg(offsets + r.x);
        int o1 = __ldg(offsets + r.y);
        unsigned short h0 = __half_as_ushort(__float2half_rn(v.x));
        unsigned short h1 = __half_as_ushort(__float2half_rn(v.y));
        edges[o0 + k.x] = (unsigned int)c.x | ((unsigned int)h0 << 16);
        edges[o1 + k.y] = (unsigned int)c.y | ((unsigned int)h1 << 16);
    } else {
        for (int e = base; e < n_edges; e++) {
            int r = __ldg(row + e);
            int pos = __ldg(offsets + r) + __ldg(rank + e);
            unsigned short hv = __half_as_ushort(__float2half_rn(__ldg(val + e)));
            edges[pos] = (unsigned int)__ldg(col + e) | ((unsigned int)hv << 16);
        }
    }

    // ---- convert: independent streaming work hides the permute latency ----
    for (int i = tid; i < total4; i += nth)
        feah[i] = pack4h(__ldg(fea + i));
}

// ---------------------------------------------------------------------------
// 5) layer 1 (R11-exact): learn1h = fp16( spmm_h(fea_h) + bias0 );
//    warp/row; uint4 edge descs (4 edges/LDG); fp16 gathers; fp32 accumulate.
//    Also restores counts==0 invariant for the next call.
// ---------------------------------------------------------------------------
__global__ void __launch_bounds__(256)
spmm1_kernel(const uint2* __restrict__ xh,
             uint2* __restrict__ yh,
             const int* __restrict__ offsets,
             const uint4* __restrict__ edges4,
             const float4* __restrict__ bias4,
             int* __restrict__ counts,
             int n_nodes) {
    int gtid = blockIdx.x * blockDim.x + threadIdx.x;
    if (gtid < n_nodes) counts[gtid] = 0;      // restore invariant
    int r = gtid >> 5;
    if (r >= n_nodes) return;
    int lane = threadIdx.x & 31;

    float4 acc = __ldg(bias4 + lane);
    int beg = __ldg(offsets + r);        // multiple of 4
    int end = __ldg(offsets + r + 1);    // multiple of 4

    int i = beg;
    for (; i + 8 <= end; i += 8) {
        uint4 d0 = __ldg(edges4 + (i >> 2));
        uint4 d1 = __ldg(edges4 + (i >> 2) + 1);
        uint2 g0 = __ldg(xh + (size_t)edge_col(d0.x) * 32 + lane);
        uint2 g1 = __ldg(xh + (size_t)edge_col(d0.y) * 32 + lane);
        uint2 g2 = __ldg(xh + (size_t)edge_col(d0.z) * 32 + lane);
        uint2 g3 = __ldg(xh + (size_t)edge_col(d0.w) * 32 + lane);
        uint2 g4 = __ldg(xh + (size_t)edge_col(d1.x) * 32 + lane);
        uint2 g5 = __ldg(xh + (size_t)edge_col(d1.y) * 32 + lane);
        uint2 g6 = __ldg(xh + (size_t)edge_col(d1.z) * 32 + lane);
        uint2 g7 = __ldg(xh + (size_t)edge_col(d1.w) * 32 + lane);
        fma4h(acc, edge_val(d0.x), g0);
        fma4h(acc, edge_val(d0.y), g1);
        fma4h(acc, edge_val(d0.z), g2);
        fma4h(acc, edge_val(d0.w), g3);
        fma4h(acc, edge_val(d1.x), g4);
        fma4h(acc, edge_val(d1.y), g5);
        fma4h(acc, edge_val(d1.z), g6);
        fma4h(acc, edge_val(d1.w), g7);
    }
    if (i < end) {                        // tail of exactly 4 edges
        uint4 d0 = __ldg(edges4 + (i >> 2));
        uint2 g0 = __ldg(xh + (size_t)edge_col(d0.x) * 32 + lane);
        uint2 g1 = __ldg(xh + (size_t)edge_col(d0.y) * 32 + lane);
        uint2 g2 = __ldg(xh + (size_t)edge_col(d0.z) * 32 + lane);
        uint2 g3 = __ldg(xh + (size_t)edge_col(d0.w) * 32 + lane);
        fma4h(acc, edge_val(d0.x), g0);
        fma4h(acc, edge_val(d0.y), g1);
        fma4h(acc, edge_val(d0.z), g2);
        fma4h(acc, edge_val(d0.w), g3);
    }

    yh[(size_t)r * 32 + lane] = pack4h(acc);
}

// ---------------------------------------------------------------------------
// 6) layer 2 + fused final (R11-exact)
// ---------------------------------------------------------------------------
__global__ void __launch_bounds__(256)
spmm2_kernel(const uint2* __restrict__ xh,       // learn1 fp16
             const uint2* __restrict__ feah,     // fea fp16
             float4* __restrict__ out,
             const int* __restrict__ offsets,
             const uint4* __restrict__ edges4,
             const float4* __restrict__ bias4,
             int n_nodes) {
    int gtid = blockIdx.x * blockDim.x + threadIdx.x;
    int r = gtid >> 5;
    if (r >= n_nodes) return;
    int lane = threadIdx.x & 31;

    float4 acc = __ldg(bias4 + lane);
    int beg = __ldg(offsets + r);
    int end = __ldg(offsets + r + 1);

    int i = beg;
    for (; i + 8 <= end; i += 8) {
        uint4 d0 = __ldg(edges4 + (i >> 2));
        uint4 d1 = __ldg(edges4 + (i >> 2) + 1);
        uint2 g0 = __ldg(xh + (size_t)edge_col(d0.x) * 32 + lane);
        uint2 g1 = __ldg(xh + (size_t)edge_col(d0.y) * 32 + lane);
        uint2 g2 = __ldg(xh + (size_t)edge_col(d0.z) * 32 + lane);
        uint2 g3 = __ldg(xh + (size_t)edge_col(d0.w) * 32 + lane);
        uint2 g4 = __ldg(xh + (size_t)edge_col(d1.x) * 32 + lane);
        uint2 g5 = __ldg(xh + (size_t)edge_col(d1.y) * 32 + lane);
        uint2 g6 = __ldg(xh + (size_t)edge_col(d1.z) * 32 + lane);
        uint2 g7 = __ldg(xh + (size_t)edge_col(d1.w) * 32 + lane);
        fma4h(acc, edge_val(d0.x), g0);
        fma4h(acc, edge_val(d0.y), g1);
        fma4h(acc, edge_val(d0.z), g2);
        fma4h(acc, edge_val(d0.w), g3);
        fma4h(acc, edge_val(d1.x), g4);
        fma4h(acc, edge_val(d1.y), g5);
        fma4h(acc, edge_val(d1.z), g6);
        fma4h(acc, edge_val(d1.w), g7);
    }
    if (i < end) {                        // tail of exactly 4 edges
        uint4 d0 = __ldg(edges4 + (i >> 2));
        uint2 g0 = __ldg(xh + (size_t)edge_col(d0.x) * 32 + lane);
        uint2 g1 = __ldg(xh + (size_t)edge_col(d0.y) * 32 + lane);
        uint2 g2 = __ldg(xh + (size_t)edge_col(d0.z) * 32 + lane);
        uint2 g3 = __ldg(xh + (size_t)edge_col(d0.w) * 32 + lane);
        fma4h(acc, edge_val(d0.x), g0);
        fma4h(acc, edge_val(d0.y), g1);
        fma4h(acc, edge_val(d0.z), g2);
        fma4h(acc, edge_val(d0.w), g3);
    }

    size_t idx = (size_t)r * 32 + lane;
    const float inv3 = 1.0f / 3.0f;
    float4 f  = unpack4h(__ldg(feah + idx));   // fp16 residual fea
    float4 l1 = unpack4h(__ldg(xh + idx));     // fp16 residual learn1
    acc.x = (f.x + l1.x + acc.x) * inv3;
    acc.y = (f.y + l1.y + acc.y) * inv3;
    acc.z = (f.z + l1.z + acc.z) * inv3;
    acc.w = (f.w + l1.w + acc.w) * inv3;
    __stcs(out + idx, acc);                    // streaming store
}

extern "C" void kernel_launch(void* const* d_in, const int* in_sizes, int n_in,
                              void* d_out, int out_size) {
    const float* fea     = (const float*)d_in[0];
    const int*   adj_row = (const int*)  d_in[1];
    const int*   adj_col = (const int*)  d_in[2];
    const float* adj_val = (const float*)d_in[3];
    const float* bias    = (const float*)d_in[4];

    int n_edges = in_sizes[1];
    int n_nodes = in_sizes[0] / HIDDEN;
    int total4  = n_nodes * 32;
    int nblocks_scan = (n_nodes + SCAN_CHUNK - 1) / SCAN_CHUNK;   // 196

    uint2* feah;    cudaGetSymbolAddress((void**)&feah,    g_feah);
    uint2* learn1h; cudaGetSymbolAddress((void**)&learn1h, g_learn1h);
    int*   counts;  cudaGetSymbolAddress((void**)&counts,  g_counts);
    int*   offs;    cudaGetSymbolAddress((void**)&offs,    g_offsets);
    int*   rank;    cudaGetSymbolAddress((void**)&rank,    g_rank);
    int*   bsum;    cudaGetSymbolAddress((void**)&bsum,    g_bsum);
    unsigned int* edges; cudaGetSymbolAddress((void**)&edges, g_edges);
    float* out = (float*)d_out;

    const int TPB = 256;

    // 1) histogram + rank (counts==0 invariant at entry)
    hist_rank_kernel<<<(n_edges + TPB - 1) / TPB, TPB>>>(adj_row, counts,
                                                         rank, n_edges);

    // 2) block sums of padded counts
    scan_bsum_kernel<<<nblocks_scan, SCAN_CHUNK>>>(counts, bsum, n_nodes);

    // 3) offsets scan + pad-edge writes
    scan_offsets_pad_kernel<<<nblocks_scan, SCAN_CHUNK>>>(counts, bsum, offs,
                                                          edges, n_nodes,
                                                          nblocks_scan);

    // 4) permute edges (2 edges/thread) + fp16 convert of fea (latency-hidden)
    {
        int threads = (n_edges + 1) / 2;
        permute_convert_kernel<<<(threads + TPB - 1) / TPB, TPB>>>(
            adj_row, adj_col, adj_val, rank, offs, edges,
            (const float4*)fea, feah, n_edges, total4);
    }

    // 5) layer 1 (+ restore counts==0)
    {
        int blocks = (n_nodes * 32 + 255) / 256;
        spmm1_kernel<<<blocks, 256>>>(feah, learn1h, offs, (const uint4*)edges,
                                      (const float4*)bias, counts, n_nodes);
    }

    // 6) layer 2 + fused final
    {
        int blocks = (n_nodes * 32 + 255) / 256;
        spmm2_kernel<<<blocks, 256>>>(learn1h, feah, (float4*)out,
                                      offs, (const uint4*)edges,
                                      (const float4*)(bias + HIDDEN), n_nodes);
    }
}